// round 1
// baseline (speedup 1.0000x reference)
#include <cuda_runtime.h>

#define N_PTS 100000
#define D 128
#define KNN 8
#define SA 132            // padded SMEM row stride (floats) for activation tiles
#define TILE_ROWS 128     // rows per CTA tile
#define THREADS 256

// 51.2 MB scratch for deduplicated layer-1 output y = x @ W1[0:128,:]
__device__ float g_y[(size_t)N_PTS * D];

// ---------------- packed f32x2 helpers ----------------
__device__ __forceinline__ unsigned long long ffma2(unsigned long long a,
                                                    unsigned long long b,
                                                    unsigned long long c) {
    unsigned long long d;
    asm("fma.rn.f32x2 %0, %1, %2, %3;" : "=l"(d) : "l"(a), "l"(b), "l"(c));
    return d;
}
__device__ __forceinline__ unsigned long long pack2(float x, float y) {
    unsigned long long d;
    asm("mov.b64 %0, {%1, %2};" : "=l"(d) : "f"(x), "f"(y));
    return d;
}
__device__ __forceinline__ float2 unpack2(unsigned long long v) {
    float2 r;
    asm("mov.b64 {%0, %1}, %2;" : "=f"(r.x), "=f"(r.y) : "l"(v));
    return r;
}

// =====================================================================
// Kernel A: y[100000,128] = x[100000,128] @ W1a[128,128]
//   (W1a = first 128 rows of W1; xyz rows + b1 folded into kernel B)
// =====================================================================
__global__ void __launch_bounds__(THREADS)
gemm1_dedup_kernel(const float* __restrict__ x, const float* __restrict__ W1) {
    extern __shared__ float smem[];
    float* xs = smem;                  // [128][SA]
    float* ws = smem + TILE_ROWS * SA; // [128][128]  (k-major: ws[k*128+f])

    const int tid = threadIdx.x;
    const int base = blockIdx.x * TILE_ROWS;

    // load W1a (rows 0..127 of W1 are contiguous) : 4096 float4
    for (int i = tid; i < 128 * 32; i += THREADS)
        ((float4*)ws)[i] = ((const float4*)W1)[i];

    // load x tile (guard tail rows)
    for (int i = tid; i < TILE_ROWS * 32; i += THREADS) {
        int r = i >> 5, c4 = i & 31;
        float4 v = make_float4(0.f, 0.f, 0.f, 0.f);
        int row = base + r;
        if (row < N_PTS) v = *(const float4*)(x + (size_t)row * D + c4 * 4);
        *(float4*)(xs + r * SA + c4 * 4) = v;
    }
    __syncthreads();

    const int fg = tid & 15, rg = tid >> 4;
    const int f0 = fg * 8, r0 = rg * 8;

    unsigned long long acc[8][4];
#pragma unroll
    for (int i = 0; i < 8; i++)
#pragma unroll
        for (int j = 0; j < 4; j++) acc[i][j] = 0ULL;

#pragma unroll 4
    for (int k = 0; k < 128; k++) {
        ulonglong2 wa = *(const ulonglong2*)(ws + k * 128 + f0);
        ulonglong2 wb = *(const ulonglong2*)(ws + k * 128 + f0 + 4);
#pragma unroll
        for (int i = 0; i < 8; i++) {
            float a = xs[(r0 + i) * SA + k];
            unsigned long long a2 = pack2(a, a);
            acc[i][0] = ffma2(a2, wa.x, acc[i][0]);
            acc[i][1] = ffma2(a2, wa.y, acc[i][1]);
            acc[i][2] = ffma2(a2, wb.x, acc[i][2]);
            acc[i][3] = ffma2(a2, wb.y, acc[i][3]);
        }
    }

#pragma unroll
    for (int i = 0; i < 8; i++) {
        int row = base + r0 + i;
        if (row < N_PTS) {
            float out8[8];
#pragma unroll
            for (int j = 0; j < 4; j++) {
                float2 t = unpack2(acc[i][j]);
                out8[2 * j] = t.x; out8[2 * j + 1] = t.y;
            }
            *(float4*)(g_y + (size_t)row * D + f0)     = *(float4*)out8;
            *(float4*)(g_y + (size_t)row * D + f0 + 4) = *(float4*)(out8 + 4);
        }
    }
}

// =====================================================================
// Kernel B: per 128 gathered rows (16 points):
//   h1 = leaky( y[idx] + xyz @ W1[128:131,:] + b1 )
//   h2 = h1 @ W2 + b2 ; out[point] = max over 8 neighbor rows
// =====================================================================
__global__ void __launch_bounds__(THREADS)
gemm2_pool_kernel(const int*   __restrict__ idx,
                  const float* __restrict__ xyz,
                  const float* __restrict__ W1,
                  const float* __restrict__ b1,
                  const float* __restrict__ W2,
                  const float* __restrict__ b2,
                  float* __restrict__ out) {
    extern __shared__ float smem[];
    float* act = smem;                   // [128][SA]
    float* w2s = smem + TILE_ROWS * SA;  // [128][128] k-major
    float* w1b = w2s + 128 * 128;        // [3][128]
    float* b1s = w1b + 3 * 128;          // [128]
    float* b2s = b1s + 128;              // [128]

    const int tid = threadIdx.x;
    const long rowbase = (long)blockIdx.x * TILE_ROWS;

    for (int i = tid; i < 128 * 32; i += THREADS)
        ((float4*)w2s)[i] = ((const float4*)W2)[i];
    for (int i = tid; i < 3 * 128; i += THREADS)
        w1b[i] = W1[128 * 128 + i];           // rows 128..130 of W1
    if (tid < 128) { b1s[tid] = b1[tid]; b2s[tid] = b2[tid]; }
    __syncthreads();

    // ---- phase 1: gather y rows + xyz term + bias + leaky-relu -> act ----
    const int lane = tid & 31, warp = tid >> 5;
    for (int rr = 0; rr < 16; rr++) {
        int r = warp * 16 + rr;
        long gr = rowbase + r;
        int id = idx[gr];
        float px = xyz[gr * 3 + 0];
        float py = xyz[gr * 3 + 1];
        float pz = xyz[gr * 3 + 2];
        float4 yv = *(const float4*)(g_y + (size_t)id * D + lane * 4);
        float4 wA = *(const float4*)(w1b + 0 * 128 + lane * 4);
        float4 wB = *(const float4*)(w1b + 1 * 128 + lane * 4);
        float4 wC = *(const float4*)(w1b + 2 * 128 + lane * 4);
        float4 bb = *(const float4*)(b1s + lane * 4);
        float4 v;
        v.x = yv.x + px * wA.x + py * wB.x + pz * wC.x + bb.x;
        v.y = yv.y + px * wA.y + py * wB.y + pz * wC.y + bb.y;
        v.z = yv.z + px * wA.z + py * wB.z + pz * wC.z + bb.z;
        v.w = yv.w + px * wA.w + py * wB.w + pz * wC.w + bb.w;
        v.x = v.x > 0.f ? v.x : 0.01f * v.x;
        v.y = v.y > 0.f ? v.y : 0.01f * v.y;
        v.z = v.z > 0.f ? v.z : 0.01f * v.z;
        v.w = v.w > 0.f ? v.w : 0.01f * v.w;
        *(float4*)(act + r * SA + lane * 4) = v;
    }
    __syncthreads();

    // ---- phase 2: GEMM2 (128x128x128 tile), acc init = b2 ----
    const int fg = tid & 15, rg = tid >> 4;
    const int f0 = fg * 8, r0 = rg * 8;

    unsigned long long bj[4];
#pragma unroll
    for (int j = 0; j < 4; j++)
        bj[j] = pack2(b2s[f0 + 2 * j], b2s[f0 + 2 * j + 1]);

    unsigned long long acc[8][4];
#pragma unroll
    for (int i = 0; i < 8; i++)
#pragma unroll
        for (int j = 0; j < 4; j++) acc[i][j] = bj[j];

#pragma unroll 4
    for (int k = 0; k < 128; k++) {
        ulonglong2 wa = *(const ulonglong2*)(w2s + k * 128 + f0);
        ulonglong2 wb = *(const ulonglong2*)(w2s + k * 128 + f0 + 4);
#pragma unroll
        for (int i = 0; i < 8; i++) {
            float a = act[(r0 + i) * SA + k];
            unsigned long long a2 = pack2(a, a);
            acc[i][0] = ffma2(a2, wa.x, acc[i][0]);
            acc[i][1] = ffma2(a2, wa.y, acc[i][1]);
            acc[i][2] = ffma2(a2, wb.x, acc[i][2]);
            acc[i][3] = ffma2(a2, wb.y, acc[i][3]);
        }
    }

    // ---- phase 3: maxpool over this thread's 8 consecutive rows (= 1 point) ----
    // rows r0..r0+7 are global rows rowbase+r0.., all belonging to point (rowbase+r0)/8
    long point = (rowbase + r0) >> 3;
    float out8[8];
#pragma unroll
    for (int j = 0; j < 4; j++) {
        float2 t = unpack2(acc[0][j]);
        float mx = t.x, my = t.y;
#pragma unroll
        for (int i = 1; i < 8; i++) {
            float2 u = unpack2(acc[i][j]);
            mx = fmaxf(mx, u.x);
            my = fmaxf(my, u.y);
        }
        out8[2 * j] = mx; out8[2 * j + 1] = my;
    }
    *(float4*)(out + (size_t)point * D + f0)     = *(float4*)out8;
    *(float4*)(out + (size_t)point * D + f0 + 4) = *(float4*)(out8 + 4);
}

// =====================================================================
extern "C" void kernel_launch(void* const* d_in, const int* in_sizes, int n_in,
                              void* d_out, int out_size) {
    const float* x    = (const float*)d_in[0];
    const int*   idx  = (const int*)d_in[1];
    const float* xyz  = (const float*)d_in[2];
    const float* W1   = (const float*)d_in[3];
    const float* b1   = (const float*)d_in[4];
    const float* W2   = (const float*)d_in[5];
    const float* b2   = (const float*)d_in[6];
    float* out = (float*)d_out;

    const int smemA = (TILE_ROWS * SA + 128 * 128) * 4;                    // 133120
    const int smemB = (TILE_ROWS * SA + 128 * 128 + 3 * 128 + 256) * 4;   // 135680
    cudaFuncSetAttribute(gemm1_dedup_kernel,
                         cudaFuncAttributeMaxDynamicSharedMemorySize, smemA);
    cudaFuncSetAttribute(gemm2_pool_kernel,
                         cudaFuncAttributeMaxDynamicSharedMemorySize, smemB);

    int gridA = (N_PTS + TILE_ROWS - 1) / TILE_ROWS;          // 782
    int gridB = (N_PTS * KNN) / TILE_ROWS;                    // 6250

    gemm1_dedup_kernel<<<gridA, THREADS, smemA>>>(x, W1);
    gemm2_pool_kernel<<<gridB, THREADS, smemB>>>(idx, xyz, W1, b1, W2, b2, out);
}

// round 3
// speedup vs baseline: 1.7443x; 1.7443x over previous
#include <cuda_runtime.h>
#include <cuda_bf16.h>
#include <cstdint>

#define N_PTS 100000
#define D 128
#define KNN 8
#define THREADS 256
#define SKP 136                      // padded bf16 row stride
#define TILE_B (128 * SKP * 2)       // 34816 bytes per bf16 tile

// scratch
__device__ float g_y[(size_t)N_PTS * D];
__device__ __align__(16) __nv_bfloat16 g_w1h[128 * SKP];
__device__ __align__(16) __nv_bfloat16 g_w1l[128 * SKP];
__device__ __align__(16) __nv_bfloat16 g_w2h[128 * SKP];
__device__ __align__(16) __nv_bfloat16 g_w2l[128 * SKP];

// ---------------- helpers ----------------
__device__ __forceinline__ uint32_t smem_u32(const void* p) {
    uint32_t a;
    asm("{ .reg .u64 t; cvta.to.shared.u64 t, %1; cvt.u32.u64 %0, t; }"
        : "=r"(a) : "l"(p));
    return a;
}
__device__ __forceinline__ uint32_t cvt_bf16x2(float hi, float lo) {
    uint32_t r;
    asm("cvt.rn.bf16x2.f32 %0, %1, %2;" : "=r"(r) : "f"(hi), "f"(lo));
    return r;
}
__device__ __forceinline__ void ldsm_x4(uint32_t addr, uint32_t* r) {
    asm volatile("ldmatrix.sync.aligned.m8n8.x4.shared.b16 {%0,%1,%2,%3}, [%4];"
                 : "=r"(r[0]), "=r"(r[1]), "=r"(r[2]), "=r"(r[3]) : "r"(addr));
}
__device__ __forceinline__ void ldsm_x2(uint32_t addr, uint32_t* r) {
    asm volatile("ldmatrix.sync.aligned.m8n8.x2.shared.b16 {%0,%1}, [%2];"
                 : "=r"(r[0]), "=r"(r[1]) : "r"(addr));
}
__device__ __forceinline__ void mma_bf16(float* d, const uint32_t* a, const uint32_t* b) {
    asm volatile(
        "mma.sync.aligned.m16n8k16.row.col.f32.bf16.bf16.f32 "
        "{%0,%1,%2,%3}, {%4,%5,%6,%7}, {%8,%9}, {%0,%1,%2,%3};"
        : "+f"(d[0]), "+f"(d[1]), "+f"(d[2]), "+f"(d[3])
        : "r"(a[0]), "r"(a[1]), "r"(a[2]), "r"(a[3]), "r"(b[0]), "r"(b[1]));
}

// split-3 MMA over one 128x128x128 tile; warp computes m32 x n64 slab
__device__ __forceinline__ void mma_slab(uint32_t sAH, uint32_t sAL,
                                         uint32_t sBH, uint32_t sBL,
                                         int lane, int m0, int n0,
                                         float d[2][8][4]) {
    // per-lane byte offsets (row-major, SKP bf16 stride)
    const uint32_t aRow = (uint32_t)(m0 + (lane & 15)) * (SKP * 2) + ((lane >> 4) * 8) * 2;
    const uint32_t bRow = (uint32_t)(n0 + (lane & 7)) * (SKP * 2) + (((lane >> 3) & 1) * 8) * 2;

#pragma unroll
    for (int ks = 0; ks < 8; ks++) {
        const uint32_t kb = ks * 32;  // 16 bf16 = 32 bytes per k-step
        uint32_t ah[2][4], al[2][4];
#pragma unroll
        for (int mt = 0; mt < 2; mt++) {
            uint32_t off = aRow + (uint32_t)mt * 16 * (SKP * 2) + kb;
            ldsm_x4(sAH + off, ah[mt]);
            ldsm_x4(sAL + off, al[mt]);
        }
        uint32_t bh[8][2], bl[8][2];
#pragma unroll
        for (int nt = 0; nt < 8; nt++) {
            uint32_t off = bRow + (uint32_t)nt * 8 * (SKP * 2) + kb;
            ldsm_x2(sBH + off, bh[nt]);
            ldsm_x2(sBL + off, bl[nt]);
        }
#pragma unroll
        for (int mt = 0; mt < 2; mt++)
#pragma unroll
            for (int nt = 0; nt < 8; nt++) {
                mma_bf16(d[mt][nt], ah[mt], bh[nt]);
                mma_bf16(d[mt][nt], al[mt], bh[nt]);
                mma_bf16(d[mt][nt], ah[mt], bl[nt]);
            }
    }
}

// =====================================================================
// prep: transpose + bf16 hi/lo split of W1[0:128,:] and W2 into padded
// [n][k] images (B operands, "col" layout)
// =====================================================================
__global__ void prep_kernel(const float* __restrict__ W1,
                            const float* __restrict__ W2) {
    int i = blockIdx.x * 256 + threadIdx.x;
    if (i >= 128 * 128) return;
    int k = i >> 7, n = i & 127;

    float v = W2[k * 128 + n];
    __nv_bfloat16 hb = __float2bfloat16(v);
    g_w2h[n * SKP + k] = hb;
    g_w2l[n * SKP + k] = __float2bfloat16(v - __bfloat162float(hb));

    v = W1[k * 128 + n];
    hb = __float2bfloat16(v);
    g_w1h[n * SKP + k] = hb;
    g_w1l[n * SKP + k] = __float2bfloat16(v - __bfloat162float(hb));
}

// =====================================================================
// Kernel A: y = x @ W1[0:128,:]   (HMMA split-3)
// smem: XH | XL | WH | WL   (4 * 34816)
// =====================================================================
__global__ void __launch_bounds__(THREADS)
gemm1_kernel(const float* __restrict__ x) {
    extern __shared__ char smc[];
    const uint32_t sb = smem_u32(smc);
    const uint32_t sXH = sb, sXL = sb + TILE_B, sWH = sb + 2 * TILE_B, sWL = sb + 3 * TILE_B;
    const int tid = threadIdx.x, w = tid >> 5, lane = tid & 31;
    const int base = blockIdx.x * 128;

    // copy weight tiles
    {
        uint4* dH = (uint4*)(smc + 2 * TILE_B);
        uint4* dL = (uint4*)(smc + 3 * TILE_B);
        const uint4* gH = (const uint4*)g_w1h;
        const uint4* gL = (const uint4*)g_w1l;
        for (int i = tid; i < TILE_B / 16; i += THREADS) { dH[i] = gH[i]; dL[i] = gL[i]; }
    }
    // load + split x tile
    {
        const int c0 = lane * 4;
#pragma unroll 2
        for (int t = 0; t < 16; t++) {
            int r = w * 16 + t;
            int row = base + r;
            float4 v = make_float4(0.f, 0.f, 0.f, 0.f);
            if (row < N_PTS) v = *(const float4*)(x + (size_t)row * D + c0);
            uint32_t h01 = cvt_bf16x2(v.y, v.x);
            uint32_t h23 = cvt_bf16x2(v.w, v.z);
            float rx = v.x - __uint_as_float(h01 << 16);
            float ry = v.y - __uint_as_float(h01 & 0xffff0000u);
            float rz = v.z - __uint_as_float(h23 << 16);
            float rw = v.w - __uint_as_float(h23 & 0xffff0000u);
            uint32_t l01 = cvt_bf16x2(ry, rx);
            uint32_t l23 = cvt_bf16x2(rw, rz);
            uint32_t off = (uint32_t)r * (SKP * 2) + c0 * 2;
            *(uint2*)(smc + off) = make_uint2(h01, h23);
            *(uint2*)(smc + TILE_B + off) = make_uint2(l01, l23);
        }
    }
    __syncthreads();

    const int m0 = (w & 3) * 32, n0 = (w >> 2) * 64;
    float d[2][8][4];
#pragma unroll
    for (int mt = 0; mt < 2; mt++)
#pragma unroll
        for (int nt = 0; nt < 8; nt++)
#pragma unroll
            for (int j = 0; j < 4; j++) d[mt][nt][j] = 0.f;

    mma_slab(sXH, sXL, sWH, sWL, lane, m0, n0, d);

    // write y
    const int g = lane >> 2, t2 = 2 * (lane & 3);
#pragma unroll
    for (int mt = 0; mt < 2; mt++) {
        int row0 = base + m0 + mt * 16 + g;
#pragma unroll
        for (int nt = 0; nt < 8; nt++) {
            int col = n0 + nt * 8 + t2;
            if (row0 < N_PTS)
                *(float2*)(g_y + (size_t)row0 * D + col) = make_float2(d[mt][nt][0], d[mt][nt][1]);
            if (row0 + 8 < N_PTS)
                *(float2*)(g_y + (size_t)(row0 + 8) * D + col) = make_float2(d[mt][nt][2], d[mt][nt][3]);
        }
    }
}

// =====================================================================
// Kernel B: act = leaky(y[idx] + xyz@W1[128:131] + b1) ; act@W2 ; maxpool+b2
// smem: AH | AL | BH | BL | b1s | b2s | w1b
// =====================================================================
#define SMB_PARAMS (4 * TILE_B)
#define SMB_TOTAL  (SMB_PARAMS + 512 + 512 + 1536)

__global__ void __launch_bounds__(THREADS)
gemm2_pool_kernel(const int*   __restrict__ idx,
                  const float* __restrict__ xyz,
                  const float* __restrict__ W1,
                  const float* __restrict__ b1,
                  const float* __restrict__ b2,
                  float* __restrict__ out) {
    extern __shared__ char smc[];
    const uint32_t sb = smem_u32(smc);
    const uint32_t sAH = sb, sAL = sb + TILE_B, sBH = sb + 2 * TILE_B, sBL = sb + 3 * TILE_B;
    float* b1s = (float*)(smc + SMB_PARAMS);
    float* b2s = (float*)(smc + SMB_PARAMS + 512);
    float* w1b = (float*)(smc + SMB_PARAMS + 1024);

    const int tid = threadIdx.x, w = tid >> 5, lane = tid & 31;
    const long rowbase = (long)blockIdx.x * 128;

    // copy W2 tiles + params
    {
        uint4* dH = (uint4*)(smc + 2 * TILE_B);
        uint4* dL = (uint4*)(smc + 3 * TILE_B);
        const uint4* gH = (const uint4*)g_w2h;
        const uint4* gL = (const uint4*)g_w2l;
        for (int i = tid; i < TILE_B / 16; i += THREADS) { dH[i] = gH[i]; dL[i] = gL[i]; }
        if (tid < 128) { b1s[tid] = b1[tid]; b2s[tid] = b2[tid]; }
        for (int i = tid; i < 3 * 128; i += THREADS) w1b[i] = W1[128 * 128 + i];
    }
    __syncthreads();   // w1b/b1s needed by phase 1

    // phase 1: gather + xyz + bias + leaky -> split bf16
    {
        const int c0 = lane * 4;
        float4 wA = *(const float4*)(w1b + 0 * 128 + c0);
        float4 wB = *(const float4*)(w1b + 1 * 128 + c0);
        float4 wC = *(const float4*)(w1b + 2 * 128 + c0);
        float4 bb = *(const float4*)(b1s + c0);
#pragma unroll 2
        for (int t = 0; t < 16; t++) {
            int r = w * 16 + t;
            long gr = rowbase + r;
            int id = __ldg(idx + gr);
            float px = __ldg(xyz + gr * 3 + 0);
            float py = __ldg(xyz + gr * 3 + 1);
            float pz = __ldg(xyz + gr * 3 + 2);
            float4 yv = *(const float4*)(g_y + (size_t)id * D + c0);
            float4 v;
            v.x = yv.x + px * wA.x + py * wB.x + pz * wC.x + bb.x;
            v.y = yv.y + px * wA.y + py * wB.y + pz * wC.y + bb.y;
            v.z = yv.z + px * wA.z + py * wB.z + pz * wC.z + bb.z;
            v.w = yv.w + px * wA.w + py * wB.w + pz * wC.w + bb.w;
            v.x = v.x > 0.f ? v.x : 0.01f * v.x;
            v.y = v.y > 0.f ? v.y : 0.01f * v.y;
            v.z = v.z > 0.f ? v.z : 0.01f * v.z;
            v.w = v.w > 0.f ? v.w : 0.01f * v.w;

            uint32_t h01 = cvt_bf16x2(v.y, v.x);
            uint32_t h23 = cvt_bf16x2(v.w, v.z);
            float rx = v.x - __uint_as_float(h01 << 16);
            float ry = v.y - __uint_as_float(h01 & 0xffff0000u);
            float rz = v.z - __uint_as_float(h23 << 16);
            float rw = v.w - __uint_as_float(h23 & 0xffff0000u);
            uint32_t l01 = cvt_bf16x2(ry, rx);
            uint32_t l23 = cvt_bf16x2(rw, rz);
            uint32_t off = (uint32_t)r * (SKP * 2) + c0 * 2;
            *(uint2*)(smc + off) = make_uint2(h01, h23);
            *(uint2*)(smc + TILE_B + off) = make_uint2(l01, l23);
        }
    }
    __syncthreads();

    const int m0 = (w & 3) * 32, n0 = (w >> 2) * 64;
    float d[2][8][4];
#pragma unroll
    for (int mt = 0; mt < 2; mt++)
#pragma unroll
        for (int nt = 0; nt < 8; nt++)
#pragma unroll
            for (int j = 0; j < 4; j++) d[mt][nt][j] = 0.f;

    mma_slab(sAH, sAL, sBH, sBL, lane, m0, n0, d);

    // epilogue: maxpool over 8 rows (lanes g=0..7 per column), +b2, store
    const int t2 = 2 * (lane & 3);
#pragma unroll
    for (int mt = 0; mt < 2; mt++) {
        long p0 = (rowbase + m0 + mt * 16) >> 3;   // rows m..m+7
        long p1 = p0 + 1;                          // rows m+8..m+15
#pragma unroll
        for (int nt = 0; nt < 8; nt++) {
            float v0 = d[mt][nt][0], v1 = d[mt][nt][1];
            float v2 = d[mt][nt][2], v3 = d[mt][nt][3];
#pragma unroll
            for (int s = 4; s < 32; s <<= 1) {
                v0 = fmaxf(v0, __shfl_xor_sync(0xffffffffu, v0, s));
                v1 = fmaxf(v1, __shfl_xor_sync(0xffffffffu, v1, s));
                v2 = fmaxf(v2, __shfl_xor_sync(0xffffffffu, v2, s));
                v3 = fmaxf(v3, __shfl_xor_sync(0xffffffffu, v3, s));
            }
            if (lane < 4) {
                int col = n0 + nt * 8 + t2;
                float bx = b2s[col], by = b2s[col + 1];
                *(float2*)(out + (size_t)p0 * D + col) = make_float2(v0 + bx, v1 + by);
                *(float2*)(out + (size_t)p1 * D + col) = make_float2(v2 + bx, v3 + by);
            }
        }
    }
}

// =====================================================================
extern "C" void kernel_launch(void* const* d_in, const int* in_sizes, int n_in,
                              void* d_out, int out_size) {
    const float* x   = (const float*)d_in[0];
    const int*   idx = (const int*)d_in[1];
    const float* xyz = (const float*)d_in[2];
    const float* W1  = (const float*)d_in[3];
    const float* b1  = (const float*)d_in[4];
    const float* W2  = (const float*)d_in[5];
    const float* b2  = (const float*)d_in[6];
    float* out = (float*)d_out;

    const int smemA = 4 * TILE_B;
    cudaFuncSetAttribute(gemm1_kernel,
                         cudaFuncAttributeMaxDynamicSharedMemorySize, smemA);
    cudaFuncSetAttribute(gemm2_pool_kernel,
                         cudaFuncAttributeMaxDynamicSharedMemorySize, SMB_TOTAL);

    prep_kernel<<<64, 256>>>(W1, W2);
    gemm1_kernel<<<(N_PTS + 127) / 128, THREADS, smemA>>>(x);
    gemm2_pool_kernel<<<(N_PTS * KNN) / 128, THREADS, SMB_TOTAL>>>(idx, xyz, W1, b1, b2, out);
}

// round 4
// speedup vs baseline: 2.7386x; 1.5700x over previous
#include <cuda_runtime.h>
#include <cuda_bf16.h>
#include <cstdint>

#define N_PTS 100000
#define D 128
#define KNN 8
#define THREADS 256
#define NSM 148
#define SKP 136                      // padded bf16 row stride
#define TILE_B (128 * SKP * 2)       // 34816 bytes per bf16 tile
#define TILES_A 782                  // ceil(100000/128)
#define TILES_BK 6250                // 800000/128

// scratch
__device__ float g_y[(size_t)N_PTS * D];
__device__ __align__(16) __nv_bfloat16 g_w1h[128 * SKP];
__device__ __align__(16) __nv_bfloat16 g_w1l[128 * SKP];
__device__ __align__(16) __nv_bfloat16 g_w2h[128 * SKP];
__device__ __align__(16) __nv_bfloat16 g_w2l[128 * SKP];

// ---------------- helpers ----------------
__device__ __forceinline__ uint32_t smem_u32(const void* p) {
    uint32_t a;
    asm("{ .reg .u64 t; cvta.to.shared.u64 t, %1; cvt.u32.u64 %0, t; }"
        : "=r"(a) : "l"(p));
    return a;
}
__device__ __forceinline__ uint32_t cvt_bf16x2(float hi, float lo) {
    uint32_t r;
    asm("cvt.rn.bf16x2.f32 %0, %1, %2;" : "=r"(r) : "f"(hi), "f"(lo));
    return r;
}
__device__ __forceinline__ void cp16(uint32_t dst, const void* src) {
    asm volatile("cp.async.cg.shared.global [%0], [%1], 16;"
                 :: "r"(dst), "l"(src) : "memory");
}
__device__ __forceinline__ void cp16z(uint32_t dst, const void* src, int srcsize) {
    asm volatile("cp.async.cg.shared.global [%0], [%1], 16, %2;"
                 :: "r"(dst), "l"(src), "r"(srcsize) : "memory");
}
__device__ __forceinline__ void cp_commit() {
    asm volatile("cp.async.commit_group;" ::: "memory");
}
__device__ __forceinline__ void cp_wait0() {
    asm volatile("cp.async.wait_group 0;" ::: "memory");
}
__device__ __forceinline__ void ldsm_x4(uint32_t addr, uint32_t* r) {
    asm volatile("ldmatrix.sync.aligned.m8n8.x4.shared.b16 {%0,%1,%2,%3}, [%4];"
                 : "=r"(r[0]), "=r"(r[1]), "=r"(r[2]), "=r"(r[3]) : "r"(addr));
}
__device__ __forceinline__ void ldsm_x2(uint32_t addr, uint32_t* r) {
    asm volatile("ldmatrix.sync.aligned.m8n8.x2.shared.b16 {%0,%1}, [%2];"
                 : "=r"(r[0]), "=r"(r[1]) : "r"(addr));
}
__device__ __forceinline__ void mma_bf16(float* d, const uint32_t* a, const uint32_t* b) {
    asm volatile(
        "mma.sync.aligned.m16n8k16.row.col.f32.bf16.bf16.f32 "
        "{%0,%1,%2,%3}, {%4,%5,%6,%7}, {%8,%9}, {%0,%1,%2,%3};"
        : "+f"(d[0]), "+f"(d[1]), "+f"(d[2]), "+f"(d[3])
        : "r"(a[0]), "r"(a[1]), "r"(a[2]), "r"(a[3]), "r"(b[0]), "r"(b[1]));
}

// split-3 MMA over one 128x128x128 tile; warp computes m32 x n64 slab
__device__ __forceinline__ void mma_slab(uint32_t sAH, uint32_t sAL,
                                         uint32_t sBH, uint32_t sBL,
                                         int lane, int m0, int n0,
                                         float d[2][8][4]) {
    const uint32_t aRow = (uint32_t)(m0 + (lane & 15)) * (SKP * 2) + ((lane >> 4) * 8) * 2;
    const uint32_t bRow = (uint32_t)(n0 + (lane & 7)) * (SKP * 2) + (((lane >> 3) & 1) * 8) * 2;

#pragma unroll
    for (int ks = 0; ks < 8; ks++) {
        const uint32_t kb = ks * 32;
        uint32_t ah[2][4], al[2][4];
#pragma unroll
        for (int mt = 0; mt < 2; mt++) {
            uint32_t off = aRow + (uint32_t)mt * 16 * (SKP * 2) + kb;
            ldsm_x4(sAH + off, ah[mt]);
            ldsm_x4(sAL + off, al[mt]);
        }
        uint32_t bh[8][2], bl[8][2];
#pragma unroll
        for (int nt = 0; nt < 8; nt++) {
            uint32_t off = bRow + (uint32_t)nt * 8 * (SKP * 2) + kb;
            ldsm_x2(sBH + off, bh[nt]);
            ldsm_x2(sBL + off, bl[nt]);
        }
#pragma unroll
        for (int mt = 0; mt < 2; mt++)
#pragma unroll
            for (int nt = 0; nt < 8; nt++) {
                mma_bf16(d[mt][nt], ah[mt], bh[nt]);
                mma_bf16(d[mt][nt], al[mt], bh[nt]);
                mma_bf16(d[mt][nt], ah[mt], bl[nt]);
            }
    }
}

// split a float4 into hi/lo bf16x2 pairs
__device__ __forceinline__ void split4(float4 v, uint2& hi, uint2& lo) {
    uint32_t h01 = cvt_bf16x2(v.y, v.x);
    uint32_t h23 = cvt_bf16x2(v.w, v.z);
    float rx = v.x - __uint_as_float(h01 << 16);
    float ry = v.y - __uint_as_float(h01 & 0xffff0000u);
    float rz = v.z - __uint_as_float(h23 << 16);
    float rw = v.w - __uint_as_float(h23 & 0xffff0000u);
    hi = make_uint2(h01, h23);
    lo = make_uint2(cvt_bf16x2(ry, rx), cvt_bf16x2(rw, rz));
}

// =====================================================================
// prep: transpose + bf16 hi/lo split of W1[0:128,:] and W2
// =====================================================================
__global__ void prep_kernel(const float* __restrict__ W1,
                            const float* __restrict__ W2) {
    int i = blockIdx.x * 256 + threadIdx.x;
    if (i >= 128 * 128) return;
    int k = i >> 7, n = i & 127;

    float v = W2[k * 128 + n];
    __nv_bfloat16 hb = __float2bfloat16(v);
    g_w2h[n * SKP + k] = hb;
    g_w2l[n * SKP + k] = __float2bfloat16(v - __bfloat162float(hb));

    v = W1[k * 128 + n];
    hb = __float2bfloat16(v);
    g_w1h[n * SKP + k] = hb;
    g_w1l[n * SKP + k] = __float2bfloat16(v - __bfloat162float(hb));
}

// =====================================================================
// Kernel A (persistent): y = x @ W1[0:128,:]
// smem: XH | XL | WH | WL | stage(64K)
// =====================================================================
#define SBA_ST   (4 * TILE_B)
#define SBA_TOT  (SBA_ST + 65536)

__device__ __forceinline__ void loadx_stage(uint32_t sb, const float* x, int t,
                                            int w, int lane) {
    uint32_t dst = sb + SBA_ST + (uint32_t)(w * 16) * 512 + lane * 16;
#pragma unroll
    for (int rr = 0; rr < 16; rr++) {
        int row = t * 128 + w * 16 + rr;
        int ok = row < N_PTS;
        const float* src = x + (size_t)(ok ? row : 0) * D + lane * 4;
        cp16z(dst + rr * 512, src, ok ? 16 : 0);
    }
}

__global__ void __launch_bounds__(THREADS, 1)
gemm1_kernel(const float* __restrict__ x) {
    extern __shared__ char smc[];
    const uint32_t sb = smem_u32(smc);
    const uint32_t sXH = sb, sXL = sb + TILE_B;
    const uint32_t sWH = sb + 2 * TILE_B, sWL = sb + 3 * TILE_B;
    const int tid = threadIdx.x, w = tid >> 5, lane = tid & 31;

    // weights once
    {
        uint4* dH = (uint4*)(smc + 2 * TILE_B);
        uint4* dL = (uint4*)(smc + 3 * TILE_B);
        const uint4* gH = (const uint4*)g_w1h;
        const uint4* gL = (const uint4*)g_w1l;
        for (int i = tid; i < TILE_B / 16; i += THREADS) { dH[i] = gH[i]; dL[i] = gL[i]; }
    }
    // prologue: stage tile t0
    int t0 = blockIdx.x;
    loadx_stage(sb, x, t0, w, lane);
    cp_commit(); cp_wait0();
    __syncthreads();

    const int m0 = (w & 3) * 32, n0 = (w >> 2) * 64;
    const int c0 = lane * 4;
    const float* st = (const float*)(smc + SBA_ST);

    for (int t = t0; t < TILES_A; t += NSM) {
        // convert stage -> XH/XL
#pragma unroll 2
        for (int rr = 0; rr < 16; rr++) {
            int r = w * 16 + rr;
            float4 v = *(const float4*)(st + (size_t)r * 128 + c0);
            uint2 hi, lo;
            split4(v, hi, lo);
            uint32_t off = (uint32_t)r * (SKP * 2) + c0 * 2;
            *(uint2*)(smc + off) = hi;
            *(uint2*)(smc + TILE_B + off) = lo;
        }
        __syncthreads();

        int tn = t + NSM;
        if (tn < TILES_A) loadx_stage(sb, x, tn, w, lane);
        cp_commit();

        float d[2][8][4];
#pragma unroll
        for (int mt = 0; mt < 2; mt++)
#pragma unroll
            for (int nt = 0; nt < 8; nt++)
#pragma unroll
                for (int j = 0; j < 4; j++) d[mt][nt][j] = 0.f;

        mma_slab(sXH, sXL, sWH, sWL, lane, m0, n0, d);

        const int g = lane >> 2, t2 = 2 * (lane & 3);
        const int base = t * 128;
#pragma unroll
        for (int mt = 0; mt < 2; mt++) {
            int row0 = base + m0 + mt * 16 + g;
#pragma unroll
            for (int nt = 0; nt < 8; nt++) {
                int col = n0 + nt * 8 + t2;
                if (row0 < N_PTS)
                    *(float2*)(g_y + (size_t)row0 * D + col) =
                        make_float2(d[mt][nt][0], d[mt][nt][1]);
                if (row0 + 8 < N_PTS)
                    *(float2*)(g_y + (size_t)(row0 + 8) * D + col) =
                        make_float2(d[mt][nt][2], d[mt][nt][3]);
            }
        }
        cp_wait0();
        __syncthreads();
    }
}

// =====================================================================
// Kernel B (persistent, pipelined):
//  gather y rows via cp.async (idx/xyz prefetched 2 tiles ahead),
//  act = leaky(y + xyz@W1[128:131] + b1) split bf16, GEMM2 HMMA, maxpool+b2
// smem: AH | AL | WH | WL | ystage | idx[2] | xyz[2] | b1 | b2 | w1b
// =====================================================================
#define SBB_Y    (4 * TILE_B)            // 139264, 65536 bytes
#define SBB_IDX  (SBB_Y + 65536)         // 204800, 2*512
#define SBB_XYZ  (SBB_IDX + 1024)        // 205824, 2*1536
#define SBB_B1   (SBB_XYZ + 3072)        // 208896
#define SBB_B2   (SBB_B1 + 512)
#define SBB_W1B  (SBB_B2 + 512)          // 209920, 1536
#define SBB_TOT  (SBB_W1B + 1536)        // 211456

__device__ __forceinline__ void issue_gather(const char* smc, uint32_t sb,
                                             int slot, int w, int lane) {
    const int* idxs = (const int*)(smc + SBB_IDX + slot * 512);
    uint32_t dst = sb + SBB_Y + (uint32_t)(w * 16) * 512 + lane * 16;
#pragma unroll
    for (int rr = 0; rr < 16; rr++) {
        int id = idxs[w * 16 + rr];
        cp16(dst + rr * 512, (const char*)g_y + (size_t)id * 512 + lane * 16);
    }
}
__device__ __forceinline__ void prefetch_ix(uint32_t sb, const int* idx,
                                            const float* xyz, int t, int slot, int tid) {
    if (tid < 32)
        cp16(sb + SBB_IDX + slot * 512 + tid * 16, idx + (size_t)t * 128 + tid * 4);
    else if (tid < 128)
        cp16(sb + SBB_XYZ + slot * 1536 + (tid - 32) * 16,
             xyz + (size_t)t * 384 + (tid - 32) * 4);
}

__global__ void __launch_bounds__(THREADS, 1)
gemm2_pool_kernel(const int*   __restrict__ idx,
                  const float* __restrict__ xyz,
                  const float* __restrict__ W1,
                  const float* __restrict__ b1,
                  const float* __restrict__ b2,
                  float* __restrict__ out) {
    extern __shared__ char smc[];
    const uint32_t sb = smem_u32(smc);
    const uint32_t sAH = sb, sAL = sb + TILE_B;
    const uint32_t sBH = sb + 2 * TILE_B, sBL = sb + 3 * TILE_B;
    float* b1s = (float*)(smc + SBB_B1);
    float* b2s = (float*)(smc + SBB_B2);
    float* w1b = (float*)(smc + SBB_W1B);

    const int tid = threadIdx.x, w = tid >> 5, lane = tid & 31;

    // weights + params once
    {
        uint4* dH = (uint4*)(smc + 2 * TILE_B);
        uint4* dL = (uint4*)(smc + 3 * TILE_B);
        const uint4* gH = (const uint4*)g_w2h;
        const uint4* gL = (const uint4*)g_w2l;
        for (int i = tid; i < TILE_B / 16; i += THREADS) { dH[i] = gH[i]; dL[i] = gL[i]; }
        if (tid < 128) { b1s[tid] = b1[tid]; b2s[tid] = b2[tid]; }
        for (int i = tid; i < 3 * 128; i += THREADS) w1b[i] = W1[128 * 128 + i];
    }

    // prologue
    const int t0 = blockIdx.x;
    prefetch_ix(sb, idx, xyz, t0, 0, tid);
    cp_commit(); cp_wait0();
    __syncthreads();
    issue_gather(smc, sb, 0, w, lane);           // y rows of t0
    if (t0 + NSM < TILES_BK) prefetch_ix(sb, idx, xyz, t0 + NSM, 1, tid);
    cp_commit(); cp_wait0();
    __syncthreads();

    const int m0 = (w & 3) * 32, n0 = (w >> 2) * 64;
    const int c0 = lane * 4;
    const float* ys = (const float*)(smc + SBB_Y);

    int p = 0;
    for (int t = t0; t < TILES_BK; t += NSM, p ^= 1) {
        // ---- convert: ystage + xyz -> AH/AL ----
        {
            const float* xz = (const float*)(smc + SBB_XYZ + p * 1536);
            float4 wA = *(const float4*)(w1b + 0 * 128 + c0);
            float4 wB = *(const float4*)(w1b + 1 * 128 + c0);
            float4 wC = *(const float4*)(w1b + 2 * 128 + c0);
            float4 bb = *(const float4*)(b1s + c0);
#pragma unroll 2
            for (int rr = 0; rr < 16; rr++) {
                int r = w * 16 + rr;
                float4 yv = *(const float4*)(ys + (size_t)r * 128 + c0);
                float px = xz[r * 3 + 0], py = xz[r * 3 + 1], pz = xz[r * 3 + 2];
                float4 v;
                v.x = yv.x + px * wA.x + py * wB.x + pz * wC.x + bb.x;
                v.y = yv.y + px * wA.y + py * wB.y + pz * wC.y + bb.y;
                v.z = yv.z + px * wA.z + py * wB.z + pz * wC.z + bb.z;
                v.w = yv.w + px * wA.w + py * wB.w + pz * wC.w + bb.w;
                v.x = v.x > 0.f ? v.x : 0.01f * v.x;
                v.y = v.y > 0.f ? v.y : 0.01f * v.y;
                v.z = v.z > 0.f ? v.z : 0.01f * v.z;
                v.w = v.w > 0.f ? v.w : 0.01f * v.w;
                uint2 hi, lo;
                split4(v, hi, lo);
                uint32_t off = (uint32_t)r * (SKP * 2) + c0 * 2;
                *(uint2*)(smc + off) = hi;
                *(uint2*)(smc + TILE_B + off) = lo;
            }
        }
        __syncthreads();

        // ---- prefetch next gather + idx/xyz two ahead ----
        int tn = t + NSM, tnn = t + 2 * NSM;
        if (tn < TILES_BK) issue_gather(smc, sb, p ^ 1, w, lane);
        if (tnn < TILES_BK) prefetch_ix(sb, idx, xyz, tnn, p, tid);
        cp_commit();

        // ---- MMA ----
        float d[2][8][4];
#pragma unroll
        for (int mt = 0; mt < 2; mt++)
#pragma unroll
            for (int nt = 0; nt < 8; nt++)
#pragma unroll
                for (int j = 0; j < 4; j++) d[mt][nt][j] = 0.f;

        mma_slab(sAH, sAL, sBH, sBL, lane, m0, n0, d);

        // ---- epilogue: maxpool over 8 rows, +b2, store ----
        const long rowbase = (long)t * 128;
        const int t2 = 2 * (lane & 3);
#pragma unroll
        for (int mt = 0; mt < 2; mt++) {
            long p0 = (rowbase + m0 + mt * 16) >> 3;
            long p1 = p0 + 1;
#pragma unroll
            for (int nt = 0; nt < 8; nt++) {
                float v0 = d[mt][nt][0], v1 = d[mt][nt][1];
                float v2 = d[mt][nt][2], v3 = d[mt][nt][3];
#pragma unroll
                for (int s = 4; s < 32; s <<= 1) {
                    v0 = fmaxf(v0, __shfl_xor_sync(0xffffffffu, v0, s));
                    v1 = fmaxf(v1, __shfl_xor_sync(0xffffffffu, v1, s));
                    v2 = fmaxf(v2, __shfl_xor_sync(0xffffffffu, v2, s));
                    v3 = fmaxf(v3, __shfl_xor_sync(0xffffffffu, v3, s));
                }
                if (lane < 4) {
                    int col = n0 + nt * 8 + t2;
                    float bx = b2s[col], by = b2s[col + 1];
                    *(float2*)(out + (size_t)p0 * D + col) = make_float2(v0 + bx, v1 + by);
                    *(float2*)(out + (size_t)p1 * D + col) = make_float2(v2 + bx, v3 + by);
                }
            }
        }
        cp_wait0();
        __syncthreads();
    }
}

// =====================================================================
extern "C" void kernel_launch(void* const* d_in, const int* in_sizes, int n_in,
                              void* d_out, int out_size) {
    const float* x   = (const float*)d_in[0];
    const int*   idx = (const int*)d_in[1];
    const float* xyz = (const float*)d_in[2];
    const float* W1  = (const float*)d_in[3];
    const float* b1  = (const float*)d_in[4];
    const float* W2  = (const float*)d_in[5];
    const float* b2  = (const float*)d_in[6];
    float* out = (float*)d_out;

    cudaFuncSetAttribute(gemm1_kernel,
                         cudaFuncAttributeMaxDynamicSharedMemorySize, SBA_TOT);
    cudaFuncSetAttribute(gemm2_pool_kernel,
                         cudaFuncAttributeMaxDynamicSharedMemorySize, SBB_TOT);

    prep_kernel<<<64, 256>>>(W1, W2);
    gemm1_kernel<<<NSM, THREADS, SBA_TOT>>>(x);
    gemm2_pool_kernel<<<NSM, THREADS, SBB_TOT>>>(idx, xyz, W1, b1, b2, out);
}

// round 5
// speedup vs baseline: 2.7901x; 1.0188x over previous
#include <cuda_runtime.h>
#include <cuda_bf16.h>
#include <cstdint>

#define N_PTS 100000
#define D 128
#define THREADS 256
#define NSM 148
#define SKPB 272               // bf16 row stride in bytes (136 bf16)
#define TILE_B 34816           // 128 * 272
#define BUF_SZ (2 * TILE_B)    // hi + lo image
#define TILES_A 782
#define TILES_BK 6250

// smem layout (shared constants for both kernels)
#define SB_WH   139264
#define SB_WL   (SB_WH + TILE_B)
#define SB_IDX  208896                  // 4 * 512
#define SB_XYZ  210944                  // 4 * 1536
#define SB_B2   217088                  // 512
#define SB_TOTB 217600
#define SB_TOTA 208896

__device__ float g_y[(size_t)N_PTS * D];

// ---------------- helpers ----------------
__device__ __forceinline__ uint32_t smem_u32(const void* p) {
    uint32_t a;
    asm("{ .reg .u64 t; cvta.to.shared.u64 t, %1; cvt.u32.u64 %0, t; }"
        : "=r"(a) : "l"(p));
    return a;
}
__device__ __forceinline__ uint32_t cvt_bf16x2(float hi, float lo) {
    uint32_t r;
    asm("cvt.rn.bf16x2.f32 %0, %1, %2;" : "=r"(r) : "f"(hi), "f"(lo));
    return r;
}
__device__ __forceinline__ void cp16(uint32_t dst, const void* src) {
    asm volatile("cp.async.cg.shared.global [%0], [%1], 16;"
                 :: "r"(dst), "l"(src) : "memory");
}
__device__ __forceinline__ void cp_commit() {
    asm volatile("cp.async.commit_group;" ::: "memory");
}
__device__ __forceinline__ void cp_wait0() {
    asm volatile("cp.async.wait_group 0;" ::: "memory");
}
__device__ __forceinline__ void ldsm_x4(uint32_t addr, uint32_t* r) {
    asm volatile("ldmatrix.sync.aligned.m8n8.x4.shared.b16 {%0,%1,%2,%3}, [%4];"
                 : "=r"(r[0]), "=r"(r[1]), "=r"(r[2]), "=r"(r[3]) : "r"(addr));
}
__device__ __forceinline__ void ldsm_x2(uint32_t addr, uint32_t* r) {
    asm volatile("ldmatrix.sync.aligned.m8n8.x2.shared.b16 {%0,%1}, [%2];"
                 : "=r"(r[0]), "=r"(r[1]) : "r"(addr));
}
__device__ __forceinline__ void mma_bf16(float* d, const uint32_t* a, const uint32_t* b) {
    asm volatile(
        "mma.sync.aligned.m16n8k16.row.col.f32.bf16.bf16.f32 "
        "{%0,%1,%2,%3}, {%4,%5,%6,%7}, {%8,%9}, {%0,%1,%2,%3};"
        : "+f"(d[0]), "+f"(d[1]), "+f"(d[2]), "+f"(d[3])
        : "r"(a[0]), "r"(a[1]), "r"(a[2]), "r"(a[3]), "r"(b[0]), "r"(b[1]));
}
__device__ __forceinline__ void split4(float4 v, uint2& hi, uint2& lo) {
    uint32_t h01 = cvt_bf16x2(v.y, v.x);
    uint32_t h23 = cvt_bf16x2(v.w, v.z);
    float rx = v.x - __uint_as_float(h01 << 16);
    float ry = v.y - __uint_as_float(h01 & 0xffff0000u);
    float rz = v.z - __uint_as_float(h23 << 16);
    float rw = v.w - __uint_as_float(h23 & 0xffff0000u);
    hi = make_uint2(h01, h23);
    lo = make_uint2(cvt_bf16x2(ry, rx), cvt_bf16x2(rw, rz));
}
__device__ __forceinline__ float4 leaky4(float4 v) {
    v.x = v.x > 0.f ? v.x : 0.01f * v.x;
    v.y = v.y > 0.f ? v.y : 0.01f * v.y;
    v.z = v.z > 0.f ? v.z : 0.01f * v.z;
    v.w = v.w > 0.f ? v.w : 0.01f * v.w;
    return v;
}
// build hi/lo bf16 split of a 128x128 weight (transposed to [n][k]) in smem
__device__ __forceinline__ void build_w(char* smc, const float* W, int tid) {
    for (int i = tid; i < 128 * 128; i += THREADS) {
        int k = i >> 7, n = i & 127;
        float v = W[i];
        __nv_bfloat16 hb = __float2bfloat16(v);
        *(__nv_bfloat16*)(smc + SB_WH + n * SKPB + k * 2) = hb;
        *(__nv_bfloat16*)(smc + SB_WL + n * SKPB + k * 2) =
            __float2bfloat16(v - __bfloat162float(hb));
    }
}

// one k-step of split-3 HMMA (48 mma) for a warp's m32 x n64 slab
__device__ __forceinline__ void mma_kstep(uint32_t abuf, uint32_t aRowOff,
                                          uint32_t bRowW, int ks, float d[2][8][4]) {
    const uint32_t kb = ks * 32;
    uint32_t ah[2][4], al[2][4];
#pragma unroll
    for (int mt = 0; mt < 2; mt++) {
        uint32_t off = abuf + aRowOff + (uint32_t)mt * 16 * SKPB + kb;
        ldsm_x4(off, ah[mt]);
        ldsm_x4(off + TILE_B, al[mt]);
    }
    uint32_t bh[8][2], bl[8][2];
#pragma unroll
    for (int nt = 0; nt < 8; nt++) {
        uint32_t off = bRowW + (uint32_t)nt * 8 * SKPB + kb;
        ldsm_x2(off, bh[nt]);
        ldsm_x2(off + TILE_B, bl[nt]);
    }
#pragma unroll
    for (int mt = 0; mt < 2; mt++)
#pragma unroll
        for (int nt = 0; nt < 8; nt++) {
            mma_bf16(d[mt][nt], ah[mt], bh[nt]);
            mma_bf16(d[mt][nt], al[mt], bh[nt]);
            mma_bf16(d[mt][nt], ah[mt], bl[nt]);
        }
}

// =====================================================================
// Kernel A (persistent, pipelined): y = x @ W1[0:128,:]
// =====================================================================
__global__ void __launch_bounds__(THREADS, 1)
gemm1_kernel(const float* __restrict__ x, const float* __restrict__ W1) {
    extern __shared__ char smc[];
    const uint32_t sb = smem_u32(smc);
    const int tid = threadIdx.x, w = tid >> 5, lane = tid & 31;
    const int w16 = w * 16, c0 = lane * 4;
    const int m0 = (w & 3) * 32, n0 = (w >> 2) * 64;
    const uint32_t aRowOff = (uint32_t)(m0 + (lane & 15)) * SKPB + ((lane >> 4) * 8) * 2;
    const uint32_t bRowW = sb + SB_WH + (uint32_t)(n0 + (lane & 7)) * SKPB +
                           (((lane >> 3) & 1) * 8) * 2;

    build_w(smc, W1, tid);

    const int t0 = blockIdx.x;
    float4 xreg[16];
    // prologue: load x(t0), convert -> buf0, load x(t0+NSM)
#pragma unroll
    for (int rr = 0; rr < 16; rr++) {
        int row = t0 * 128 + w16 + rr;
        xreg[rr] = *(const float4*)(x + (size_t)(row < N_PTS ? row : 0) * D + c0);
    }
#pragma unroll
    for (int rr = 0; rr < 16; rr++) {
        uint2 hi, lo; split4(xreg[rr], hi, lo);
        uint32_t off = (uint32_t)(w16 + rr) * SKPB + c0 * 2;
        *(uint2*)(smc + off) = hi;
        *(uint2*)(smc + TILE_B + off) = lo;
    }
    {
        int tn = t0 + NSM;
#pragma unroll
        for (int rr = 0; rr < 16; rr++) {
            int row = tn * 128 + w16 + rr;
            xreg[rr] = *(const float4*)(x + (size_t)(row < N_PTS ? row : 0) * D + c0);
        }
    }
    __syncthreads();

    int p = 0;
    for (int t = t0; t < TILES_A; t += NSM, p ^= 1) {
        const uint32_t abuf = sb + p * BUF_SZ;
        char* cb = smc + (p ^ 1) * BUF_SZ;
        const int t2 = t + 2 * NSM;

        float d[2][8][4];
#pragma unroll
        for (int mt = 0; mt < 2; mt++)
#pragma unroll
            for (int nt = 0; nt < 8; nt++)
#pragma unroll
                for (int j = 0; j < 4; j++) d[mt][nt][j] = 0.f;

#pragma unroll
        for (int ks = 0; ks < 8; ks++) {
            mma_kstep(abuf, aRowOff, bRowW, ks, d);
            // interleaved: convert rows 2ks,2ks+1 of tile t+NSM, load tile t+2NSM
            const int rr = 2 * ks;
#pragma unroll
            for (int q = 0; q < 2; q++) {
                uint2 hi, lo; split4(xreg[rr + q], hi, lo);
                uint32_t off = (uint32_t)(w16 + rr + q) * SKPB + c0 * 2;
                *(uint2*)(cb + off) = hi;
                *(uint2*)(cb + TILE_B + off) = lo;
                int row = t2 * 128 + w16 + rr + q;
                xreg[rr + q] =
                    *(const float4*)(x + (size_t)(row < N_PTS ? row : 0) * D + c0);
            }
        }

        // epilogue: store y(t)
        const int g = lane >> 2, tt2 = 2 * (lane & 3);
        const int base = t * 128;
#pragma unroll
        for (int mt = 0; mt < 2; mt++) {
            int row0 = base + m0 + mt * 16 + g;
#pragma unroll
            for (int nt = 0; nt < 8; nt++) {
                int col = n0 + nt * 8 + tt2;
                if (row0 < N_PTS)
                    *(float2*)(g_y + (size_t)row0 * D + col) =
                        make_float2(d[mt][nt][0], d[mt][nt][1]);
                if (row0 + 8 < N_PTS)
                    *(float2*)(g_y + (size_t)(row0 + 8) * D + col) =
                        make_float2(d[mt][nt][2], d[mt][nt][3]);
            }
        }
        __syncthreads();
    }
}

// =====================================================================
// Kernel B (persistent, fully pipelined):
//  act = leaky(y[idx] + xyz@W1[128:131] + b1) -> split bf16 (interleaved
//  into previous tile's MMA); GEMM2 HMMA split-3; maxpool(8) + b2
// =====================================================================
__device__ __forceinline__ void prefetch_ix(uint32_t sb, const int* idx,
                                            const float* xyz, int tile, int slot,
                                            int tid) {
    if (tile >= TILES_BK) tile = TILES_BK - 1;
    if (tid < 32)
        cp16(sb + SB_IDX + slot * 512 + tid * 16, idx + (size_t)tile * 128 + tid * 4);
    else if (tid < 128)
        cp16(sb + SB_XYZ + slot * 1536 + (tid - 32) * 16,
             xyz + (size_t)tile * 384 + (tid - 32) * 4);
}

__global__ void __launch_bounds__(THREADS, 1)
gemm2_pool_kernel(const int*   __restrict__ idx,
                  const float* __restrict__ xyz,
                  const float* __restrict__ W1,
                  const float* __restrict__ b1,
                  const float* __restrict__ W2,
                  const float* __restrict__ b2,
                  float* __restrict__ out) {
    extern __shared__ char smc[];
    const uint32_t sb = smem_u32(smc);
    const int tid = threadIdx.x, w = tid >> 5, lane = tid & 31;
    const int w16 = w * 16, c0 = lane * 4;
    const int m0 = (w & 3) * 32, n0 = (w >> 2) * 64;
    const uint32_t aRowOff = (uint32_t)(m0 + (lane & 15)) * SKPB + ((lane >> 4) * 8) * 2;
    const uint32_t bRowW = sb + SB_WH + (uint32_t)(n0 + (lane & 7)) * SKPB +
                           (((lane >> 3) & 1) * 8) * 2;
    const char* gyc = (const char*)g_y;
    const uint32_t lane16 = lane * 16;
    float* b2s = (float*)(smc + SB_B2);

    build_w(smc, W2, tid);
    if (tid < 128) b2s[tid] = b2[tid];

    // per-thread loop-invariant layer-1 params (registers)
    const float4 wA = *(const float4*)(W1 + 128 * 128 + c0);
    const float4 wB = *(const float4*)(W1 + 129 * 128 + c0);
    const float4 wC = *(const float4*)(W1 + 130 * 128 + c0);
    const float4 bb = *(const float4*)(b1 + c0);

    const int t0 = blockIdx.x;
    // slots 0..3 <- tiles t0 .. t0+3*NSM
    prefetch_ix(sb, idx, xyz, t0, 0, tid);
    prefetch_ix(sb, idx, xyz, t0 + NSM, 1, tid);
    prefetch_ix(sb, idx, xyz, t0 + 2 * NSM, 2, tid);
    cp_commit();
    cp_wait0();
    __syncthreads();

    float4 yreg[16];
    // gather y(t0), convert -> buf0
    {
        const int* idxs = (const int*)(smc + SB_IDX);
        const float* xz = (const float*)(smc + SB_XYZ);
#pragma unroll
        for (int rr = 0; rr < 16; rr++) {
            int id = idxs[w16 + rr];
            yreg[rr] = *(const float4*)(gyc + (size_t)id * 512 + lane16);
        }
#pragma unroll
        for (int rr = 0; rr < 16; rr++) {
            int r = w16 + rr;
            float px = xz[r * 3], py = xz[r * 3 + 1], pz = xz[r * 3 + 2];
            float4 v = yreg[rr];
            v.x += px * wA.x + py * wB.x + pz * wC.x + bb.x;
            v.y += px * wA.y + py * wB.y + pz * wC.y + bb.y;
            v.z += px * wA.z + py * wB.z + pz * wC.z + bb.z;
            v.w += px * wA.w + py * wB.w + pz * wC.w + bb.w;
            v = leaky4(v);
            uint2 hi, lo; split4(v, hi, lo);
            uint32_t off = (uint32_t)r * SKPB + c0 * 2;
            *(uint2*)(smc + off) = hi;
            *(uint2*)(smc + TILE_B + off) = lo;
        }
        // gather y(t0+NSM)
        const int* idxs1 = (const int*)(smc + SB_IDX + 512);
#pragma unroll
        for (int rr = 0; rr < 16; rr++) {
            int id = idxs1[w16 + rr];
            yreg[rr] = *(const float4*)(gyc + (size_t)id * 512 + lane16);
        }
    }
    prefetch_ix(sb, idx, xyz, t0 + 3 * NSM, 3, tid);
    cp_commit();
    __syncthreads();

    int p = 0, i = 0;
    for (int t = t0; t < TILES_BK; t += NSM, i++, p ^= 1) {
        const float* xz = (const float*)(smc + SB_XYZ + ((i + 1) & 3) * 1536);
        const int* idxs2 = (const int*)(smc + SB_IDX + ((i + 2) & 3) * 512);
        const uint32_t abuf = sb + p * BUF_SZ;
        char* cb = smc + (p ^ 1) * BUF_SZ;

        float d[2][8][4];
#pragma unroll
        for (int mt = 0; mt < 2; mt++)
#pragma unroll
            for (int nt = 0; nt < 8; nt++)
#pragma unroll
                for (int j = 0; j < 4; j++) d[mt][nt][j] = 0.f;

#pragma unroll
        for (int ks = 0; ks < 8; ks++) {
            mma_kstep(abuf, aRowOff, bRowW, ks, d);
            // interleaved: convert 2 rows of tile t+NSM, gather 2 rows of t+2NSM
            const int rr = 2 * ks;
#pragma unroll
            for (int q = 0; q < 2; q++) {
                int r = w16 + rr + q;
                float px = xz[r * 3], py = xz[r * 3 + 1], pz = xz[r * 3 + 2];
                float4 v = yreg[rr + q];
                v.x += px * wA.x + py * wB.x + pz * wC.x + bb.x;
                v.y += px * wA.y + py * wB.y + pz * wC.y + bb.y;
                v.z += px * wA.z + py * wB.z + pz * wC.z + bb.z;
                v.w += px * wA.w + py * wB.w + pz * wC.w + bb.w;
                v = leaky4(v);
                uint2 hi, lo; split4(v, hi, lo);
                uint32_t off = (uint32_t)r * SKPB + c0 * 2;
                *(uint2*)(cb + off) = hi;
                *(uint2*)(cb + TILE_B + off) = lo;
                int id = idxs2[r];
                yreg[rr + q] = *(const float4*)(gyc + (size_t)id * 512 + lane16);
            }
        }

        cp_wait0();                                 // groups <= i+3 done
        prefetch_ix(sb, idx, xyz, t + 4 * NSM, i & 3, tid);
        cp_commit();

        // epilogue: maxpool over 8 rows, +b2, store
        const long rowbase = (long)t * 128;
        const int tt2 = 2 * (lane & 3);
#pragma unroll
        for (int mt = 0; mt < 2; mt++) {
            long p0 = (rowbase + m0 + mt * 16) >> 3;
            long p1 = p0 + 1;
#pragma unroll
            for (int nt = 0; nt < 8; nt++) {
                float v0 = d[mt][nt][0], v1 = d[mt][nt][1];
                float v2 = d[mt][nt][2], v3 = d[mt][nt][3];
#pragma unroll
                for (int s = 4; s < 32; s <<= 1) {
                    v0 = fmaxf(v0, __shfl_xor_sync(0xffffffffu, v0, s));
                    v1 = fmaxf(v1, __shfl_xor_sync(0xffffffffu, v1, s));
                    v2 = fmaxf(v2, __shfl_xor_sync(0xffffffffu, v2, s));
                    v3 = fmaxf(v3, __shfl_xor_sync(0xffffffffu, v3, s));
                }
                if (lane < 4) {
                    int col = n0 + nt * 8 + tt2;
                    float bx = b2s[col], by = b2s[col + 1];
                    *(float2*)(out + (size_t)p0 * D + col) = make_float2(v0 + bx, v1 + by);
                    *(float2*)(out + (size_t)p1 * D + col) = make_float2(v2 + bx, v3 + by);
                }
            }
        }
        __syncthreads();
    }
}

// =====================================================================
extern "C" void kernel_launch(void* const* d_in, const int* in_sizes, int n_in,
                              void* d_out, int out_size) {
    const float* x   = (const float*)d_in[0];
    const int*   idx = (const int*)d_in[1];
    const float* xyz = (const float*)d_in[2];
    const float* W1  = (const float*)d_in[3];
    const float* b1  = (const float*)d_in[4];
    const float* W2  = (const float*)d_in[5];
    const float* b2  = (const float*)d_in[6];
    float* out = (float*)d_out;

    cudaFuncSetAttribute(gemm1_kernel,
                         cudaFuncAttributeMaxDynamicSharedMemorySize, SB_TOTA);
    cudaFuncSetAttribute(gemm2_pool_kernel,
                         cudaFuncAttributeMaxDynamicSharedMemorySize, SB_TOTB);

    gemm1_kernel<<<NSM, THREADS, SB_TOTA>>>(x, W1);
    gemm2_pool_kernel<<<NSM, THREADS, SB_TOTB>>>(idx, xyz, W1, b1, W2, b2, out);
}

// round 7
// speedup vs baseline: 3.1819x; 1.1404x over previous
#include <cuda_runtime.h>
#include <cuda_bf16.h>
#include <cstdint>

#define N_PTS 100000
#define D 128
#define NSM 148
#define SKPB 272               // bf16 row stride in bytes (136 bf16)
#define TILE_B 34816           // 128 * 272
#define BUF_SZ (2 * TILE_B)    // hi + lo image
#define TILES_A 782
#define TILES_BK 6250

// smem layout (shared by both kernels)
#define SB_WH   139264
#define SB_WL   (SB_WH + TILE_B)
#define SB_IDX  208896                  // 4 * 512
#define SB_XYZ  210944                  // 4 * 1536
#define SB_B2   217088                  // 512
#define SB_TOTB 217600
#define SB_TOTA 208896

__device__ float g_y[(size_t)N_PTS * D];

// ---------------- helpers ----------------
__device__ __forceinline__ uint32_t smem_u32(const void* p) {
    uint32_t a;
    asm("{ .reg .u64 t; cvta.to.shared.u64 t, %1; cvt.u32.u64 %0, t; }"
        : "=r"(a) : "l"(p));
    return a;
}
__device__ __forceinline__ uint32_t cvt_bf16x2(float hi, float lo) {
    uint32_t r;
    asm("cvt.rn.bf16x2.f32 %0, %1, %2;" : "=r"(r) : "f"(hi), "f"(lo));
    return r;
}
__device__ __forceinline__ void cp16(uint32_t dst, const void* src) {
    asm volatile("cp.async.cg.shared.global [%0], [%1], 16;"
                 :: "r"(dst), "l"(src) : "memory");
}
__device__ __forceinline__ void cp_commit() {
    asm volatile("cp.async.commit_group;" ::: "memory");
}
__device__ __forceinline__ void cp_wait0() {
    asm volatile("cp.async.wait_group 0;" ::: "memory");
}
__device__ __forceinline__ void ldsm_x4(uint32_t addr, uint32_t* r) {
    asm volatile("ldmatrix.sync.aligned.m8n8.x4.shared.b16 {%0,%1,%2,%3}, [%4];"
                 : "=r"(r[0]), "=r"(r[1]), "=r"(r[2]), "=r"(r[3]) : "r"(addr));
}
__device__ __forceinline__ void ldsm_x2(uint32_t addr, uint32_t* r) {
    asm volatile("ldmatrix.sync.aligned.m8n8.x2.shared.b16 {%0,%1}, [%2];"
                 : "=r"(r[0]), "=r"(r[1]) : "r"(addr));
}
__device__ __forceinline__ void mma_bf16(float* d, const uint32_t* a, const uint32_t* b) {
    asm volatile(
        "mma.sync.aligned.m16n8k16.row.col.f32.bf16.bf16.f32 "
        "{%0,%1,%2,%3}, {%4,%5,%6,%7}, {%8,%9}, {%0,%1,%2,%3};"
        : "+f"(d[0]), "+f"(d[1]), "+f"(d[2]), "+f"(d[3])
        : "r"(a[0]), "r"(a[1]), "r"(a[2]), "r"(a[3]), "r"(b[0]), "r"(b[1]));
}
__device__ __forceinline__ void split4(float4 v, uint2& hi, uint2& lo) {
    uint32_t h01 = cvt_bf16x2(v.y, v.x);
    uint32_t h23 = cvt_bf16x2(v.w, v.z);
    float rx = v.x - __uint_as_float(h01 << 16);
    float ry = v.y - __uint_as_float(h01 & 0xffff0000u);
    float rz = v.z - __uint_as_float(h23 << 16);
    float rw = v.w - __uint_as_float(h23 & 0xffff0000u);
    hi = make_uint2(h01, h23);
    lo = make_uint2(cvt_bf16x2(ry, rx), cvt_bf16x2(rw, rz));
}
__device__ __forceinline__ float4 leaky4(float4 v) {
    v.x = v.x > 0.f ? v.x : 0.01f * v.x;
    v.y = v.y > 0.f ? v.y : 0.01f * v.y;
    v.z = v.z > 0.f ? v.z : 0.01f * v.z;
    v.w = v.w > 0.f ? v.w : 0.01f * v.w;
    return v;
}
__device__ __forceinline__ void build_w(char* smc, const float* W, int tid, int nthr) {
    for (int i = tid; i < 128 * 128; i += nthr) {
        int k = i >> 7, n = i & 127;
        float v = W[i];
        __nv_bfloat16 hb = __float2bfloat16(v);
        *(__nv_bfloat16*)(smc + SB_WH + n * SKPB + k * 2) = hb;
        *(__nv_bfloat16*)(smc + SB_WL + n * SKPB + k * 2) =
            __float2bfloat16(v - __bfloat162float(hb));
    }
}
__device__ __forceinline__ void prefetch_ix(uint32_t sb, const int* idx,
                                            const float* xyz, int tile, int slot,
                                            int tid) {
    if (tile >= TILES_BK) tile = TILES_BK - 1;
    if (tid < 32)
        cp16(sb + SB_IDX + slot * 512 + tid * 16, idx + (size_t)tile * 128 + tid * 4);
    else if (tid < 128)
        cp16(sb + SB_XYZ + slot * 1536 + (tid - 32) * 16,
             xyz + (size_t)tile * 384 + (tid - 32) * 4);
}

// =====================================================================
// Kernel A (persistent, pipelined, 256 thr): y = x @ W1[0:128,:]
// =====================================================================
__device__ __forceinline__ void mma_kstep64(uint32_t abuf, uint32_t aRowOff,
                                            uint32_t bRowW, int ks, float d[2][8][4]) {
    const uint32_t kb = ks * 32;
    uint32_t ah[2][4], al[2][4];
#pragma unroll
    for (int mt = 0; mt < 2; mt++) {
        uint32_t off = abuf + aRowOff + (uint32_t)mt * 16 * SKPB + kb;
        ldsm_x4(off, ah[mt]);
        ldsm_x4(off + TILE_B, al[mt]);
    }
    uint32_t bh[8][2], bl[8][2];
#pragma unroll
    for (int nt = 0; nt < 8; nt++) {
        uint32_t off = bRowW + (uint32_t)nt * 8 * SKPB + kb;
        ldsm_x2(off, bh[nt]);
        ldsm_x2(off + TILE_B, bl[nt]);
    }
#pragma unroll
    for (int mt = 0; mt < 2; mt++)
#pragma unroll
        for (int nt = 0; nt < 8; nt++) {
            mma_bf16(d[mt][nt], ah[mt], bh[nt]);
            mma_bf16(d[mt][nt], al[mt], bh[nt]);
            mma_bf16(d[mt][nt], ah[mt], bl[nt]);
        }
}

__global__ void __launch_bounds__(256, 1)
gemm1_kernel(const float* __restrict__ x, const float* __restrict__ W1) {
    extern __shared__ char smc[];
    const uint32_t sb = smem_u32(smc);
    const int tid = threadIdx.x, w = tid >> 5, lane = tid & 31;
    const int w16 = w * 16, c0 = lane * 4;
    const int m0 = (w & 3) * 32, n0 = (w >> 2) * 64;
    const uint32_t aRowOff = (uint32_t)(m0 + (lane & 15)) * SKPB + (lane >> 4) * 16;
    const uint32_t bRowW = sb + SB_WH + (uint32_t)(n0 + (lane & 7)) * SKPB +
                           ((lane >> 3) & 1) * 16;

    build_w(smc, W1, tid, 256);

    const int t0 = blockIdx.x;
    float4 xreg[16];
#pragma unroll
    for (int rr = 0; rr < 16; rr++) {
        int row = t0 * 128 + w16 + rr;
        xreg[rr] = *(const float4*)(x + (size_t)(row < N_PTS ? row : 0) * D + c0);
    }
#pragma unroll
    for (int rr = 0; rr < 16; rr++) {
        uint2 hi, lo; split4(xreg[rr], hi, lo);
        uint32_t off = (uint32_t)(w16 + rr) * SKPB + c0 * 2;
        *(uint2*)(smc + off) = hi;
        *(uint2*)(smc + TILE_B + off) = lo;
    }
    {
        int tn = t0 + NSM;
#pragma unroll
        for (int rr = 0; rr < 16; rr++) {
            int row = tn * 128 + w16 + rr;
            xreg[rr] = *(const float4*)(x + (size_t)(row < N_PTS ? row : 0) * D + c0);
        }
    }
    __syncthreads();

    int p = 0;
    for (int t = t0; t < TILES_A; t += NSM, p ^= 1) {
        const uint32_t abuf = sb + p * BUF_SZ;
        char* cb = smc + (p ^ 1) * BUF_SZ;
        const int t2 = t + 2 * NSM;

        float d[2][8][4];
#pragma unroll
        for (int mt = 0; mt < 2; mt++)
#pragma unroll
            for (int nt = 0; nt < 8; nt++)
#pragma unroll
                for (int j = 0; j < 4; j++) d[mt][nt][j] = 0.f;

#pragma unroll
        for (int ks = 0; ks < 8; ks++) {
            mma_kstep64(abuf, aRowOff, bRowW, ks, d);
            const int rr = 2 * ks;
#pragma unroll
            for (int q = 0; q < 2; q++) {
                uint2 hi, lo; split4(xreg[rr + q], hi, lo);
                uint32_t off = (uint32_t)(w16 + rr + q) * SKPB + c0 * 2;
                *(uint2*)(cb + off) = hi;
                *(uint2*)(cb + TILE_B + off) = lo;
                int row = t2 * 128 + w16 + rr + q;
                xreg[rr + q] =
                    *(const float4*)(x + (size_t)(row < N_PTS ? row : 0) * D + c0);
            }
        }

        const int g = lane >> 2, tt2 = 2 * (lane & 3);
        const int base = t * 128;
#pragma unroll
        for (int mt = 0; mt < 2; mt++) {
            int row0 = base + m0 + mt * 16 + g;
#pragma unroll
            for (int nt = 0; nt < 8; nt++) {
                int col = n0 + nt * 8 + tt2;
                if (row0 < N_PTS)
                    *(float2*)(g_y + (size_t)row0 * D + col) =
                        make_float2(d[mt][nt][0], d[mt][nt][1]);
                if (row0 + 8 < N_PTS)
                    *(float2*)(g_y + (size_t)(row0 + 8) * D + col) =
                        make_float2(d[mt][nt][2], d[mt][nt][3]);
            }
        }
        __syncthreads();
    }
}

// =====================================================================
// Kernel B (persistent, 512 thr, 16 warps, m32xn32 slabs, x4 B loads)
// =====================================================================
// one k-step: 8 LDSM + 24 HMMA for a warp's m32 x n32 slab
__device__ __forceinline__ void mma_kstep32(uint32_t abuf, uint32_t aRowOff,
                                            uint32_t bRow4, int ks, float d[2][4][4]) {
    const uint32_t kb = ks * 32;
    uint32_t ah[2][4], al[2][4];
#pragma unroll
    for (int mt = 0; mt < 2; mt++) {
        uint32_t off = abuf + aRowOff + (uint32_t)mt * 16 * SKPB + kb;
        ldsm_x4(off, ah[mt]);
        ldsm_x4(off + TILE_B, al[mt]);
    }
    uint32_t bh[8], bl[8];   // [rows n0..15 | rows n0+16..31]
    ldsm_x4(bRow4 + kb, bh);
    ldsm_x4(bRow4 + 16 * SKPB + kb, bh + 4);
    ldsm_x4(bRow4 + TILE_B + kb, bl);
    ldsm_x4(bRow4 + TILE_B + 16 * SKPB + kb, bl + 4);
#pragma unroll
    for (int mt = 0; mt < 2; mt++)
#pragma unroll
        for (int nt = 0; nt < 4; nt++) {
            const uint32_t* bph = &bh[(nt >> 1) * 4 + (nt & 1) * 2];
            const uint32_t* bpl = &bl[(nt >> 1) * 4 + (nt & 1) * 2];
            mma_bf16(d[mt][nt], ah[mt], bph);
            mma_bf16(d[mt][nt], al[mt], bph);
            mma_bf16(d[mt][nt], ah[mt], bpl);
        }
}

__global__ void __launch_bounds__(512, 1)
gemm2_pool_kernel(const int*   __restrict__ idx,
                  const float* __restrict__ xyz,
                  const float* __restrict__ W1,
                  const float* __restrict__ b1,
                  const float* __restrict__ W2,
                  const float* __restrict__ b2,
                  float* __restrict__ out) {
    extern __shared__ char smc[];
    const uint32_t sb = smem_u32(smc);
    const int tid = threadIdx.x, w = tid >> 5, lane = tid & 31;
    const int w8 = w * 8, c0 = lane * 4;
    const int m0 = (w & 3) * 32, n0 = (w >> 2) * 32;
    const uint32_t aRowOff = (uint32_t)(m0 + (lane & 15)) * SKPB + (lane >> 4) * 16;
    const uint32_t bRow4 = sb + SB_WH +
        (uint32_t)(n0 + (lane & 7) + ((lane >> 4) & 1) * 8) * SKPB +
        ((lane >> 3) & 1) * 16;
    const char* gyc = (const char*)g_y;
    const uint32_t lane16 = lane * 16;
    float* b2s = (float*)(smc + SB_B2);

    build_w(smc, W2, tid, 512);
    if (tid < 128) b2s[tid] = b2[tid];

    const float4 wA = *(const float4*)(W1 + 128 * 128 + c0);
    const float4 wB = *(const float4*)(W1 + 129 * 128 + c0);
    const float4 wC = *(const float4*)(W1 + 130 * 128 + c0);
    const float4 bb = *(const float4*)(b1 + c0);

    const int t0 = blockIdx.x;
    // slots 0..2 <- tiles t0, t0+NSM, t0+2NSM
    prefetch_ix(sb, idx, xyz, t0, 0, tid);
    prefetch_ix(sb, idx, xyz, t0 + NSM, 1, tid);
    prefetch_ix(sb, idx, xyz, t0 + 2 * NSM, 2, tid);
    cp_commit();
    cp_wait0();
    __syncthreads();

    // prologue: gather+convert tile t0 -> buf0 (8 rows per warp)
    {
        const int* idxs = (const int*)(smc + SB_IDX);
        const float* xz = (const float*)(smc + SB_XYZ);
#pragma unroll
        for (int rr = 0; rr < 8; rr++) {
            int r = w8 + rr;
            int id = idxs[r];
            float4 v = *(const float4*)(gyc + (size_t)id * 512 + lane16);
            float px = xz[r * 3], py = xz[r * 3 + 1], pz = xz[r * 3 + 2];
            v.x += px * wA.x + py * wB.x + pz * wC.x + bb.x;
            v.y += px * wA.y + py * wB.y + pz * wC.y + bb.y;
            v.z += px * wA.z + py * wB.z + pz * wC.z + bb.z;
            v.w += px * wA.w + py * wB.w + pz * wC.w + bb.w;
            v = leaky4(v);
            uint2 hi, lo; split4(v, hi, lo);
            uint32_t off = (uint32_t)r * SKPB + c0 * 2;
            *(uint2*)(smc + off) = hi;
            *(uint2*)(smc + TILE_B + off) = lo;
        }
    }
    __syncthreads();

    float4 yring[4];
    int p = 0, i = 0;
    for (int t = t0; t < TILES_BK; t += NSM, i++, p ^= 1) {
        const int* idx1 = (const int*)(smc + SB_IDX + ((i + 1) & 3) * 512);
        const float* xz1 = (const float*)(smc + SB_XYZ + ((i + 1) & 3) * 1536);
        const uint32_t abuf = sb + p * BUF_SZ;
        char* cb = smc + (p ^ 1) * BUF_SZ;

        float d[2][4][4];
#pragma unroll
        for (int mt = 0; mt < 2; mt++)
#pragma unroll
            for (int nt = 0; nt < 4; nt++)
#pragma unroll
                for (int j = 0; j < 4; j++) d[mt][nt][j] = 0.f;

#pragma unroll
        for (int ks = 0; ks < 8; ks++) {
            mma_kstep32(abuf, aRowOff, bRow4, ks, d);
            // pipeline next tile's A: CONVERT (rows gathered 2 steps ago)
            // BEFORE gathering into the same ring slots.
            if (ks >= 2 && ks < 6) {
                const int rr = 2 * (ks - 2);
#pragma unroll
                for (int q = 0; q < 2; q++) {
                    int r = w8 + rr + q;
                    float px = xz1[r * 3], py = xz1[r * 3 + 1], pz = xz1[r * 3 + 2];
                    float4 v = yring[(rr + q) & 3];
                    v.x += px * wA.x + py * wB.x + pz * wC.x + bb.x;
                    v.y += px * wA.y + py * wB.y + pz * wC.y + bb.y;
                    v.z += px * wA.z + py * wB.z + pz * wC.z + bb.z;
                    v.w += px * wA.w + py * wB.w + pz * wC.w + bb.w;
                    v = leaky4(v);
                    uint2 hi, lo; split4(v, hi, lo);
                    uint32_t off = (uint32_t)r * SKPB + c0 * 2;
                    *(uint2*)(cb + off) = hi;
                    *(uint2*)(cb + TILE_B + off) = lo;
                }
            }
            if (ks < 4) {
                const int rr = 2 * ks;
#pragma unroll
                for (int q = 0; q < 2; q++) {
                    int id = idx1[w8 + rr + q];
                    yring[(rr + q) & 3] =
                        *(const float4*)(gyc + (size_t)id * 512 + lane16);
                }
            }
        }

        // wait for prefetch committed at iter i-1 (covers slot used at i+1),
        // then prefetch 3 tiles ahead
        cp_wait0();
        prefetch_ix(sb, idx, xyz, t + 3 * NSM, (i + 3) & 3, tid);
        cp_commit();

        // epilogue: maxpool over 8 rows, +b2, store
        const long rowbase = (long)t * 128;
        const int tt2 = 2 * (lane & 3);
#pragma unroll
        for (int mt = 0; mt < 2; mt++) {
            long p0 = (rowbase + m0 + mt * 16) >> 3;
            long p1 = p0 + 1;
#pragma unroll
            for (int nt = 0; nt < 4; nt++) {
                float v0 = d[mt][nt][0], v1 = d[mt][nt][1];
                float v2 = d[mt][nt][2], v3 = d[mt][nt][3];
#pragma unroll
                for (int s = 4; s < 32; s <<= 1) {
                    v0 = fmaxf(v0, __shfl_xor_sync(0xffffffffu, v0, s));
                    v1 = fmaxf(v1, __shfl_xor_sync(0xffffffffu, v1, s));
                    v2 = fmaxf(v2, __shfl_xor_sync(0xffffffffu, v2, s));
                    v3 = fmaxf(v3, __shfl_xor_sync(0xffffffffu, v3, s));
                }
                if (lane < 4) {
                    int col = n0 + nt * 8 + tt2;
                    float bx = b2s[col], by = b2s[col + 1];
                    *(float2*)(out + (size_t)p0 * D + col) = make_float2(v0 + bx, v1 + by);
                    *(float2*)(out + (size_t)p1 * D + col) = make_float2(v2 + bx, v3 + by);
                }
            }
        }
        __syncthreads();
    }
}

// =====================================================================
extern "C" void kernel_launch(void* const* d_in, const int* in_sizes, int n_in,
                              void* d_out, int out_size) {
    const float* x   = (const float*)d_in[0];
    const int*   idx = (const int*)d_in[1];
    const float* xyz = (const float*)d_in[2];
    const float* W1  = (const float*)d_in[3];
    const float* b1  = (const float*)d_in[4];
    const float* W2  = (const float*)d_in[5];
    const float* b2  = (const float*)d_in[6];
    float* out = (float*)d_out;

    cudaFuncSetAttribute(gemm1_kernel,
                         cudaFuncAttributeMaxDynamicSharedMemorySize, SB_TOTA);
    cudaFuncSetAttribute(gemm2_pool_kernel,
                         cudaFuncAttributeMaxDynamicSharedMemorySize, SB_TOTB);

    gemm1_kernel<<<NSM, 256, SB_TOTA>>>(x, W1);
    gemm2_pool_kernel<<<NSM, 512, SB_TOTB>>>(idx, xyz, W1, b1, W2, b2, out);
}